// round 8
// baseline (speedup 1.0000x reference)
#include <cuda_runtime.h>
#include <math.h>
#include <cstdint>

#define BB 8
#define NN 2048
#define CC 512
#define KK 8
#define EPSF 1e-6f
#define GENO_RATIO 0.1f

// ---------------- scratch ----------------
__device__ int   g_cnt[BB][KK];
__device__ int   g_idx[BB][KK][NN];
__device__ float g_wgt[BB][KK][NN];
__device__ float g_mass[BB][KK];
__device__ float g_hw[BB][KK][CC];
__device__ float g_glog[BB][KK];

__device__ __forceinline__ float tf32r(float x) {
    uint32_t u;
    asm("cvt.rna.tf32.f32 %0, %1;" : "=r"(u) : "f"(x));
    return __uint_as_float(u);
}

// ---------------- prep: zero hw/cnt/mass + glog ----------------
__global__ __launch_bounds__(256) void prep_kernel(const float* __restrict__ geno_vec,
                                                   const float* __restrict__ geno_w,
                                                   const float* __restrict__ geno_b) {
    if (blockIdx.x < 32) {
        int t = blockIdx.x * 256 + threadIdx.x;
        float* hw = &g_hw[0][0][0];
#pragma unroll
        for (int i = 0; i < 4; i++) hw[t + i * 8192] = 0.f;
    } else {
        int t = threadIdx.x;
        if (t < BB * KK) {
            ((int*)g_cnt)[t] = 0;
            ((float*)g_mass)[t] = 0.f;
            int b = t / KK, k = t % KK;
            float acc = 0.f;
            for (int c = 0; c < CC; c++) acc += geno_vec[b * CC + c] * geno_w[c * KK + k];
            g_glog[b][k] = GENO_RATIO * (acc + geno_b[k]);
        }
    }
}

// ---------------- gating ----------------
__global__ __launch_bounds__(256) void gate_kernel(const float* __restrict__ tokens,
                                                   const float* __restrict__ gate_w,
                                                   const float* __restrict__ gate_b) {
    __shared__ float gwT[KK][CC];
    int tid = threadIdx.x;
    for (int i = tid; i < CC * KK; i += 256) gwT[i & 7][i >> 3] = gate_w[i];
    __syncthreads();

    int warp = blockIdx.x * 8 + (tid >> 5);
    int lane = tid & 31;
    if (warp >= BB * NN) return;
    int b = warp / NN, n = warp % NN;
    const float* x = tokens + (size_t)(b * NN + n) * CC;

    float acc[KK];
#pragma unroll
    for (int k = 0; k < KK; k++) acc[k] = 0.f;
#pragma unroll
    for (int i = 0; i < 4; i++) {
        int c = i * 128 + lane * 4;
        float4 xv = *(const float4*)(x + c);
#pragma unroll
        for (int k = 0; k < KK; k++) {
            float4 gv = *(const float4*)&gwT[k][c];
            acc[k] += xv.x * gv.x + xv.y * gv.y + xv.z * gv.z + xv.w * gv.w;
        }
    }
#pragma unroll
    for (int k = 0; k < KK; k++) {
#pragma unroll
        for (int off = 16; off; off >>= 1)
            acc[k] += __shfl_xor_sync(0xffffffffu, acc[k], off);
    }

    if (lane == 0) {
        float lg[KK];
#pragma unroll
        for (int k = 0; k < KK; k++) lg[k] = acc[k] + gate_b[k] + g_glog[b][k];
        int i0 = 0; float v0 = lg[0];
#pragma unroll
        for (int k = 1; k < KK; k++) if (lg[k] > v0) { v0 = lg[k]; i0 = k; }
        int i1 = -1; float v1 = -3.4e38f;
#pragma unroll
        for (int k = 0; k < KK; k++) if (k != i0 && lg[k] > v1) { v1 = lg[k]; i1 = k; }
        float e1 = __expf(v1 - v0);
        float inv = 1.f / (1.f + e1);
        float w0 = fmaxf(inv, EPSF), w1v = fmaxf(e1 * inv, EPSF);
        float s = 1.f / (w0 + w1v);
        w0 *= s; w1v *= s;
        int p0 = atomicAdd(&g_cnt[b][i0], 1);
        g_idx[b][i0][p0] = n; g_wgt[b][i0][p0] = w0;
        atomicAdd(&g_mass[b][i0], w0);
        int p1 = atomicAdd(&g_cnt[b][i1], 1);
        g_idx[b][i1][p1] = n; g_wgt[b][i1][p1] = w1v;
        atomicAdd(&g_mass[b][i1], w1v);
    }
}

// ---------------- ffn1: fragment-packed smem, vector LDS feeds ----------------
#define BM 128
#define BN 128
#define BKC 32
#define NSTAGE (CC / BKC)     // 16
// A: 32 regions (mb 0..7 x kk 0..3), each 32 slots x 4 floats, stride 132 floats
// B: 64 regions (nb 0..15 x kk 0..3), each 32 slots x 2 floats, stride 66 floats
#define A_REG_STR 132
#define B_REG_STR 66
#define A_FLOATS (32 * A_REG_STR)   // 4224
#define B_FLOATS (64 * B_REG_STR)   // 4224
#define STAGE_FLOATS (A_FLOATS + B_FLOATS)

__device__ __forceinline__ void mma1688(float* c, const uint32_t* a, const uint32_t* bf) {
    asm volatile(
        "mma.sync.aligned.m16n8k8.row.col.f32.tf32.tf32.f32 "
        "{%0,%1,%2,%3}, {%4,%5,%6,%7}, {%8,%9}, {%0,%1,%2,%3};"
        : "+f"(c[0]), "+f"(c[1]), "+f"(c[2]), "+f"(c[3])
        : "r"(a[0]), "r"(a[1]), "r"(a[2]), "r"(a[3]), "r"(bf[0]), "r"(bf[1]));
}

__global__ __launch_bounds__(256, 1) void ffn1_mma_kernel(const float* __restrict__ tokens,
                                                          const float* __restrict__ w1,
                                                          const float* __restrict__ b1) {
    extern __shared__ float smem[];
    const int bk = blockIdx.z;
    const int b = bk >> 3, k = bk & 7;
    const int cnt = g_cnt[b][k];
    const int m0 = blockIdx.y * BM;
    if (m0 >= cnt) return;
    const int d0 = blockIdx.x * BN;

    float* As0 = smem;
    float* Bs0 = smem + A_FLOATS;
    float* As1 = smem + STAGE_FLOATS;
    float* Bs1 = smem + STAGE_FLOATS + A_FLOATS;
    int*   ns_s = (int*)(smem + 2 * STAGE_FLOATS);
    float* wt_s = (float*)(ns_s + BM);

    const int tid = threadIdx.x;
    const int lane = tid & 31, wid = tid >> 5;
    const int wm = wid >> 2, wn = wid & 3;     // 2 x 4 warp grid
    const int l4 = lane >> 2, lm = lane & 3;

    if (tid < BM) {
        int m = m0 + tid;
        if (m < cnt) { ns_s[tid] = g_idx[b][k][m]; wt_s[tid] = g_wgt[b][k][m]; }
        else         { ns_s[tid] = -1;             wt_s[tid] = 0.f; }
    }
    __syncthreads();

    // ---- X loader mapping: token xm = tid>>1, parity p picks khalf ----
    const int xm  = tid >> 1;
    const int xp_par = tid & 1;
    const int xmb = xm >> 4;            // m16 block
    const int xl4 = xm & 7;
    const int xmh = (xm >> 3) & 1;
    const int xn = ns_s[xm];
    const float* xp = (xn >= 0) ? tokens + ((size_t)(b * NN + xn)) * CC : nullptr;
    // X store base offset (elem varies by j only via slot): region (xmb*4+i)
    const int x_elem = xmh + 2 * xp_par;

    // ---- W loader mapping ----
    const int wr  = tid >> 3;           // k-row within stage 0..31
    const int wjb = tid & 7;
    const int wkk = wr >> 3;
    const int wlm = wr & 3;
    const int wkh = (wr >> 2) & 1;
    const float* wp = w1 + ((size_t)k * CC + wr) * CC + d0;

    float4 xv[4], wv[4];
#define LOAD_STAGE(s) do {                                                        \
        int c0_ = (s) * BKC;                                                      \
        _Pragma("unroll")                                                         \
        for (int i = 0; i < 4; i++)                                               \
            xv[i] = xp ? *(const float4*)(xp + c0_ + i * 8 + xp_par * 4)          \
                       : make_float4(0.f, 0.f, 0.f, 0.f);                         \
        _Pragma("unroll")                                                         \
        for (int i = 0; i < 4; i++)                                               \
            wv[i] = *(const float4*)(wp + (size_t)c0_ * CC + (wjb + i * 8) * 4);  \
    } while (0)

#define STORE_STAGE(Ast, Bst) do {                                                \
        _Pragma("unroll")                                                         \
        for (int i = 0; i < 4; i++) {                                             \
            float* base = (Ast) + (xmb * 4 + i) * A_REG_STR + x_elem;             \
            base[(0 * 8 + xl4) * 4] = tf32r(xv[i].x);                             \
            base[(1 * 8 + xl4) * 4] = tf32r(xv[i].y);                             \
            base[(2 * 8 + xl4) * 4] = tf32r(xv[i].z);                             \
            base[(3 * 8 + xl4) * 4] = tf32r(xv[i].w);                             \
        }                                                                         \
        _Pragma("unroll")                                                         \
        for (int i = 0; i < 4; i++) {                                             \
            float v4_[4] = { wv[i].x, wv[i].y, wv[i].z, wv[i].w };                \
            _Pragma("unroll")                                                     \
            for (int j = 0; j < 4; j++) {                                         \
                int nb_ = (wjb >> 1) + i * 4;                                     \
                int permB_ = j * 8 + wlm * 2 + (wjb & 1);                         \
                (Bst)[(nb_ * 4 + wkk) * B_REG_STR + permB_ * 2 + wkh] =           \
                    tf32r(v4_[j]);                                                \
            }                                                                     \
        }                                                                         \
    } while (0)

    // fragment slots for mainloop loads
    const int aslot = lm * 8 + l4;                        // perm_A
    const int bslot = (l4 & 3) * 8 + lm * 2 + (l4 >> 2);  // perm_B

    float acc[4][4][4];
#pragma unroll
    for (int mf = 0; mf < 4; mf++)
#pragma unroll
        for (int nf = 0; nf < 4; nf++)
#pragma unroll
            for (int q = 0; q < 4; q++) acc[mf][nf][q] = 0.f;

    LOAD_STAGE(0);
    STORE_STAGE(As0, Bs0);
    __syncthreads();

    for (int s = 0; s < NSTAGE; s++) {
        const float* Ast = (s & 1) ? As1 : As0;
        const float* Bst = (s & 1) ? Bs1 : Bs0;
        if (s + 1 < NSTAGE) LOAD_STAGE(s + 1);

#pragma unroll
        for (int kk = 0; kk < 4; kk++) {
            uint32_t a[4][4], bf[4][2];
#pragma unroll
            for (int mf = 0; mf < 4; mf++) {
                float4 av = *(const float4*)(Ast + ((wm * 4 + mf) * 4 + kk) * A_REG_STR + aslot * 4);
                a[mf][0] = __float_as_uint(av.x);
                a[mf][1] = __float_as_uint(av.y);
                a[mf][2] = __float_as_uint(av.z);
                a[mf][3] = __float_as_uint(av.w);
            }
#pragma unroll
            for (int nf = 0; nf < 4; nf++) {
                float2 bv = *(const float2*)(Bst + ((wn * 4 + nf) * 4 + kk) * B_REG_STR + bslot * 2);
                bf[nf][0] = __float_as_uint(bv.x);
                bf[nf][1] = __float_as_uint(bv.y);
            }
#pragma unroll
            for (int mf = 0; mf < 4; mf++)
#pragma unroll
                for (int nf = 0; nf < 4; nf++)
                    mma1688(acc[mf][nf], a[mf], bf[nf]);
        }

        if (s + 1 < NSTAGE) {
            __syncthreads();
            if (s & 1) STORE_STAGE(As0, Bs0);
            else       STORE_STAGE(As1, Bs1);
            __syncthreads();
        }
    }

    // epilogue: relu(acc + b1) * wt, reduce over token rows
    float bias[4][2];
#pragma unroll
    for (int nf = 0; nf < 4; nf++)
#pragma unroll
        for (int j = 0; j < 2; j++)
            bias[nf][j] = __ldg(b1 + k * CC + d0 + wn * 32 + nf * 8 + lm * 2 + j);

    float part[4][2];
#pragma unroll
    for (int nf = 0; nf < 4; nf++) { part[nf][0] = 0.f; part[nf][1] = 0.f; }

#pragma unroll
    for (int mf = 0; mf < 4; mf++) {
        int r0 = wm * 64 + mf * 16 + l4;
        float w0 = wt_s[r0], w1r = wt_s[r0 + 8];
#pragma unroll
        for (int nf = 0; nf < 4; nf++)
#pragma unroll
            for (int j = 0; j < 2; j++)
                part[nf][j] += fmaxf(acc[mf][nf][j] + bias[nf][j], 0.f) * w0
                             + fmaxf(acc[mf][nf][2 + j] + bias[nf][j], 0.f) * w1r;
    }
#pragma unroll
    for (int off = 4; off < 32; off <<= 1)
#pragma unroll
        for (int nf = 0; nf < 4; nf++)
#pragma unroll
            for (int j = 0; j < 2; j++)
                part[nf][j] += __shfl_xor_sync(0xffffffffu, part[nf][j], off);

    if (l4 == 0) {
        float* hw = &g_hw[b][k][0];
#pragma unroll
        for (int nf = 0; nf < 4; nf++)
#pragma unroll
            for (int j = 0; j < 2; j++)
                atomicAdd(hw + d0 + wn * 32 + nf * 8 + lm * 2 + j, part[nf][j]);
    }
}

// ---------------- centers: batched over b, w2 read once (+loss fused) ----------
__global__ __launch_bounds__(256) void centers_kernel(const float* __restrict__ w2,
                                                      const float* __restrict__ b2,
                                                      float* __restrict__ out, int out_size) {
    const int k = blockIdx.x;
    const int e0 = blockIdx.y * 32;
    __shared__ float hw_s[BB][CC];
    __shared__ float part[8][32][9];
    const int tid = threadIdx.x;

    for (int i = tid; i < BB * CC; i += 256)
        hw_s[i >> 9][i & 511] = g_hw[i >> 9][k][i & 511];
    __syncthreads();

    const int e = e0 + (tid & 31);
    const int ds = (tid >> 5) * 64;
    float acc[BB];
#pragma unroll
    for (int b = 0; b < BB; b++) acc[b] = 0.f;

    const float* w2p = w2 + ((size_t)k * CC + ds) * CC + e;
#pragma unroll 4
    for (int d = 0; d < 64; d++) {
        float w = w2p[(size_t)d * CC];
#pragma unroll
        for (int b = 0; b < BB; b++) acc[b] += hw_s[b][ds + d] * w;
    }
#pragma unroll
    for (int b = 0; b < BB; b++) part[tid >> 5][tid & 31][b] = acc[b];
    __syncthreads();

    {
        const int b = tid >> 5, el = tid & 31;
        float s = 0.f;
#pragma unroll
        for (int sl = 0; sl < 8; sl++) s += part[sl][el][b];
        float mass = g_mass[b][k];
        float inv = 1.f / fmaxf(mass, EPSF);
        float val = (s + b2[k * CC + e0 + el] * mass) * inv;
        int o = (b * KK + k) * CC + e0 + el;
        if (o < out_size) out[o] = val;
    }

    if (blockIdx.x == 0 && blockIdx.y == 0 && tid == 0) {
        float usage[KK], mean = 0.f;
#pragma unroll
        for (int kk = 0; kk < KK; kk++) {
            int s = 0;
            for (int bb = 0; bb < BB; bb++) s += g_cnt[bb][kk];
            usage[kk] = (float)s / (float)(BB * NN);
            mean += usage[kk];
        }
        mean /= (float)KK;
        float var = 0.f;
#pragma unroll
        for (int kk = 0; kk < KK; kk++) { float d = usage[kk] - mean; var += d * d; }
        var /= (float)KK;
        float denom = mean + EPSF;
        out[out_size - 1] = var / (denom * denom);
    }
}

// ---------------- launch ----------------
extern "C" void kernel_launch(void* const* d_in, const int* in_sizes, int n_in,
                              void* d_out, int out_size) {
    const float* tokens   = (const float*)d_in[0];
    const float* geno_vec = (const float*)d_in[1];
    const float* gate_w   = (const float*)d_in[2];
    const float* gate_b   = (const float*)d_in[3];
    const float* geno_w   = (const float*)d_in[4];
    const float* geno_b   = (const float*)d_in[5];
    const float* w1       = (const float*)d_in[6];
    const float* b1       = (const float*)d_in[7];
    const float* w2       = (const float*)d_in[8];
    const float* b2       = (const float*)d_in[9];
    float* out = (float*)d_out;

    const int smem_bytes = (2 * STAGE_FLOATS) * 4 + BM * 8;
    cudaFuncSetAttribute(ffn1_mma_kernel, cudaFuncAttributeMaxDynamicSharedMemorySize, smem_bytes);

    prep_kernel<<<33, 256>>>(geno_vec, geno_w, geno_b);
    gate_kernel<<<(BB * NN + 7) / 8, 256>>>(tokens, gate_w, gate_b);
    {
        dim3 g(CC / BN, NN / BM, BB * KK);  // 4 x 16 x 64
        ffn1_mma_kernel<<<g, 256, smem_bytes>>>(tokens, w1, b1);
    }
    {
        dim3 g(KK, CC / 32);
        centers_kernel<<<g, 256>>>(w2, b2, out, out_size);
    }
}

// round 10
// speedup vs baseline: 1.5954x; 1.5954x over previous
#include <cuda_runtime.h>
#include <math.h>
#include <cstdint>

#define BB 8
#define NN 2048
#define CC 512
#define KK 8
#define EPSF 1e-6f
#define GENO_RATIO 0.1f

// ---------------- scratch ----------------
__device__ int   g_cnt[BB][KK];
__device__ int   g_idx[BB][KK][NN];
__device__ float g_wgt[BB][KK][NN];
__device__ float g_mass[BB][KK];
__device__ float g_hw[BB][KK][CC];
__device__ float g_glog[BB][KK];

__device__ __forceinline__ float tf32r(float x) {
    uint32_t u;
    asm("cvt.rna.tf32.f32 %0, %1;" : "=r"(u) : "f"(x));
    return __uint_as_float(u);
}

// ---------------- prep: zero hw/cnt/mass + glog ----------------
__global__ __launch_bounds__(256) void prep_kernel(const float* __restrict__ geno_vec,
                                                   const float* __restrict__ geno_w,
                                                   const float* __restrict__ geno_b) {
    if (blockIdx.x < 32) {
        int t = blockIdx.x * 256 + threadIdx.x;
        float* hw = &g_hw[0][0][0];
#pragma unroll
        for (int i = 0; i < 4; i++) hw[t + i * 8192] = 0.f;
    } else {
        int t = threadIdx.x;
        if (t < BB * KK) {
            ((int*)g_cnt)[t] = 0;
            ((float*)g_mass)[t] = 0.f;
            int b = t / KK, k = t % KK;
            float acc = 0.f;
            for (int c = 0; c < CC; c++) acc += geno_vec[b * CC + c] * geno_w[c * KK + k];
            g_glog[b][k] = GENO_RATIO * (acc + geno_b[k]);
        }
    }
}

// ---------------- gating ----------------
__global__ __launch_bounds__(256) void gate_kernel(const float* __restrict__ tokens,
                                                   const float* __restrict__ gate_w,
                                                   const float* __restrict__ gate_b) {
    __shared__ float gwT[KK][CC];
    int tid = threadIdx.x;
    for (int i = tid; i < CC * KK; i += 256) gwT[i & 7][i >> 3] = gate_w[i];
    __syncthreads();

    int warp = blockIdx.x * 8 + (tid >> 5);
    int lane = tid & 31;
    if (warp >= BB * NN) return;
    int b = warp / NN, n = warp % NN;
    const float* x = tokens + (size_t)(b * NN + n) * CC;

    float acc[KK];
#pragma unroll
    for (int k = 0; k < KK; k++) acc[k] = 0.f;
#pragma unroll
    for (int i = 0; i < 4; i++) {
        int c = i * 128 + lane * 4;
        float4 xv = *(const float4*)(x + c);
#pragma unroll
        for (int k = 0; k < KK; k++) {
            float4 gv = *(const float4*)&gwT[k][c];
            acc[k] += xv.x * gv.x + xv.y * gv.y + xv.z * gv.z + xv.w * gv.w;
        }
    }
#pragma unroll
    for (int k = 0; k < KK; k++) {
#pragma unroll
        for (int off = 16; off; off >>= 1)
            acc[k] += __shfl_xor_sync(0xffffffffu, acc[k], off);
    }

    if (lane == 0) {
        float lg[KK];
#pragma unroll
        for (int k = 0; k < KK; k++) lg[k] = acc[k] + gate_b[k] + g_glog[b][k];
        int i0 = 0; float v0 = lg[0];
#pragma unroll
        for (int k = 1; k < KK; k++) if (lg[k] > v0) { v0 = lg[k]; i0 = k; }
        int i1 = -1; float v1 = -3.4e38f;
#pragma unroll
        for (int k = 0; k < KK; k++) if (k != i0 && lg[k] > v1) { v1 = lg[k]; i1 = k; }
        float e1 = __expf(v1 - v0);
        float inv = 1.f / (1.f + e1);
        float w0 = fmaxf(inv, EPSF), w1v = fmaxf(e1 * inv, EPSF);
        float s = 1.f / (w0 + w1v);
        w0 *= s; w1v *= s;
        int p0 = atomicAdd(&g_cnt[b][i0], 1);
        g_idx[b][i0][p0] = n; g_wgt[b][i0][p0] = w0;
        atomicAdd(&g_mass[b][i0], w0);
        int p1 = atomicAdd(&g_cnt[b][i1], 1);
        g_idx[b][i1][p1] = n; g_wgt[b][i1][p1] = w1v;
        atomicAdd(&g_mass[b][i1], w1v);
    }
}

// ---------------- ffn1 via mma.sync tf32: BN=256, 64x64 warp tiles ----------------
#define BM 128
#define BN 256
#define BKC 32
#define NSTAGE (CC / BKC)     // 16
#define XS_STRIDE (BM + 8)    // 136
#define WS_STRIDE (BN + 8)    // 264
#define XTILE_FLOATS (BKC * XS_STRIDE)
#define WTILE_FLOATS (BKC * WS_STRIDE)
#define STAGE_FLOATS (XTILE_FLOATS + WTILE_FLOATS)

__device__ __forceinline__ void mma1688(float* c, const uint32_t* a, const uint32_t* bf) {
    asm volatile(
        "mma.sync.aligned.m16n8k8.row.col.f32.tf32.tf32.f32 "
        "{%0,%1,%2,%3}, {%4,%5,%6,%7}, {%8,%9}, {%0,%1,%2,%3};"
        : "+f"(c[0]), "+f"(c[1]), "+f"(c[2]), "+f"(c[3])
        : "r"(a[0]), "r"(a[1]), "r"(a[2]), "r"(a[3]), "r"(bf[0]), "r"(bf[1]));
}

__global__ __launch_bounds__(256, 1) void ffn1_mma_kernel(const float* __restrict__ tokens,
                                                          const float* __restrict__ w1,
                                                          const float* __restrict__ b1) {
    extern __shared__ float smem[];
    const int bk = blockIdx.z;
    const int b = bk >> 3, k = bk & 7;
    const int cnt = g_cnt[b][k];
    const int m0 = blockIdx.y * BM;
    if (m0 >= cnt) return;
    const int d0 = blockIdx.x * BN;

    float* Xs0 = smem;
    float* Ws0 = smem + XTILE_FLOATS;
    float* Xs1 = smem + STAGE_FLOATS;
    float* Ws1 = smem + STAGE_FLOATS + XTILE_FLOATS;
    int*   ns_s = (int*)(smem + 2 * STAGE_FLOATS);
    float* wt_s = (float*)(ns_s + BM);

    const int tid = threadIdx.x;
    const int lane = tid & 31, wid = tid >> 5;
    const int wm = wid >> 2, wn = wid & 3;     // 2m x 4n warp grid, 64x64 tiles
    const int l4 = lane >> 2, lm = lane & 3;

    if (tid < BM) {
        int m = m0 + tid;
        if (m < cnt) { ns_s[tid] = g_idx[b][k][m]; wt_s[tid] = g_wgt[b][k][m]; }
        else         { ns_s[tid] = -1;             wt_s[tid] = 0.f; }
    }
    __syncthreads();

    const int xm = tid >> 1;              // token row 0..127
    const int xjb = (tid & 1) * 4;        // float4 index base (0 or 4)
    const int xn = ns_s[xm];
    const float* xp = (xn >= 0) ? tokens + ((size_t)(b * NN + xn)) * CC : nullptr;
    const int wr = tid >> 3;              // w row (c) 0..31
    const int wjb = tid & 7;              // float4 col base
    const float* wp = w1 + ((size_t)k * CC + wr) * CC + d0;

    float4 xv[4], wv[8];
#define LOAD_STAGE(s) do {                                                        \
        int c0_ = (s) * BKC;                                                      \
        _Pragma("unroll")                                                         \
        for (int i = 0; i < 4; i++)                                               \
            xv[i] = xp ? *(const float4*)(xp + c0_ + (xjb + i) * 4)               \
                       : make_float4(0.f, 0.f, 0.f, 0.f);                         \
        _Pragma("unroll")                                                         \
        for (int i = 0; i < 8; i++)                                               \
            wv[i] = *(const float4*)(wp + (size_t)c0_ * CC + (wjb + i * 8) * 4);  \
    } while (0)

#define STORE_STAGE(Xst, Wst) do {                                                \
        _Pragma("unroll")                                                         \
        for (int i = 0; i < 4; i++) {                                             \
            int kl = (xjb + i) * 4;                                               \
            (Xst)[(kl + 0) * XS_STRIDE + xm] = tf32r(xv[i].x);                    \
            (Xst)[(kl + 1) * XS_STRIDE + xm] = tf32r(xv[i].y);                    \
            (Xst)[(kl + 2) * XS_STRIDE + xm] = tf32r(xv[i].z);                    \
            (Xst)[(kl + 3) * XS_STRIDE + xm] = tf32r(xv[i].w);                    \
        }                                                                         \
        _Pragma("unroll")                                                         \
        for (int i = 0; i < 8; i++) {                                             \
            float4 t;                                                             \
            t.x = tf32r(wv[i].x); t.y = tf32r(wv[i].y);                           \
            t.z = tf32r(wv[i].z); t.w = tf32r(wv[i].w);                           \
            *(float4*)((Wst) + wr * WS_STRIDE + (wjb + i * 8) * 4) = t;           \
        }                                                                         \
    } while (0)

    float acc[4][8][4];
#pragma unroll
    for (int mf = 0; mf < 4; mf++)
#pragma unroll
        for (int nf = 0; nf < 8; nf++)
#pragma unroll
            for (int q = 0; q < 4; q++) acc[mf][nf][q] = 0.f;

    LOAD_STAGE(0);
    STORE_STAGE(Xs0, Ws0);
    __syncthreads();

    for (int s = 0; s < NSTAGE; s++) {
        const float* Xst = (s & 1) ? Xs1 : Xs0;
        const float* Wst = (s & 1) ? Ws1 : Ws0;
        if (s + 1 < NSTAGE) LOAD_STAGE(s + 1);

#pragma unroll
        for (int kk = 0; kk < 4; kk++) {
            uint32_t a[4][4], bf[8][2];
            const float* xk0 = Xst + (kk * 8 + lm) * XS_STRIDE;
            const float* xk4 = Xst + (kk * 8 + lm + 4) * XS_STRIDE;
#pragma unroll
            for (int mf = 0; mf < 4; mf++) {
                int mrow = wm * 64 + mf * 16 + l4;
                a[mf][0] = __float_as_uint(xk0[mrow]);
                a[mf][1] = __float_as_uint(xk0[mrow + 8]);
                a[mf][2] = __float_as_uint(xk4[mrow]);
                a[mf][3] = __float_as_uint(xk4[mrow + 8]);
            }
            const float* wk0 = Wst + (kk * 8 + lm) * WS_STRIDE;
            const float* wk4 = Wst + (kk * 8 + lm + 4) * WS_STRIDE;
#pragma unroll
            for (int nf = 0; nf < 8; nf++) {
                int ncol = wn * 64 + nf * 8 + l4;
                bf[nf][0] = __float_as_uint(wk0[ncol]);
                bf[nf][1] = __float_as_uint(wk4[ncol]);
            }
#pragma unroll
            for (int mf = 0; mf < 4; mf++)
#pragma unroll
                for (int nf = 0; nf < 8; nf++)
                    mma1688(acc[mf][nf], a[mf], bf[nf]);
        }

        if (s + 1 < NSTAGE) {
            __syncthreads();
            if (s & 1) STORE_STAGE(Xs0, Ws0);
            else       STORE_STAGE(Xs1, Ws1);
            __syncthreads();
        }
    }

    // epilogue: relu(acc + b1) * wt, reduce over token rows
    float bias[8][2];
#pragma unroll
    for (int nf = 0; nf < 8; nf++)
#pragma unroll
        for (int j = 0; j < 2; j++)
            bias[nf][j] = __ldg(b1 + k * CC + d0 + wn * 64 + nf * 8 + lm * 2 + j);

    float part[8][2];
#pragma unroll
    for (int nf = 0; nf < 8; nf++) { part[nf][0] = 0.f; part[nf][1] = 0.f; }

#pragma unroll
    for (int mf = 0; mf < 4; mf++) {
        int r0 = wm * 64 + mf * 16 + l4;
        float w0 = wt_s[r0], w1r = wt_s[r0 + 8];
#pragma unroll
        for (int nf = 0; nf < 8; nf++)
#pragma unroll
            for (int j = 0; j < 2; j++)
                part[nf][j] += fmaxf(acc[mf][nf][j] + bias[nf][j], 0.f) * w0
                             + fmaxf(acc[mf][nf][2 + j] + bias[nf][j], 0.f) * w1r;
    }
#pragma unroll
    for (int off = 4; off < 32; off <<= 1)
#pragma unroll
        for (int nf = 0; nf < 8; nf++)
#pragma unroll
            for (int j = 0; j < 2; j++)
                part[nf][j] += __shfl_xor_sync(0xffffffffu, part[nf][j], off);

    if (l4 == 0) {
        float* hw = &g_hw[b][k][0];
#pragma unroll
        for (int nf = 0; nf < 8; nf++)
#pragma unroll
            for (int j = 0; j < 2; j++)
                atomicAdd(hw + d0 + wn * 64 + nf * 8 + lm * 2 + j, part[nf][j]);
    }
}

// ---------------- centers: batched over b, w2 read once (+loss fused) ----------
__global__ __launch_bounds__(256) void centers_kernel(const float* __restrict__ w2,
                                                      const float* __restrict__ b2,
                                                      float* __restrict__ out, int out_size) {
    const int k = blockIdx.x;
    const int e0 = blockIdx.y * 32;
    __shared__ float hw_s[BB][CC];
    __shared__ float part[8][32][9];
    const int tid = threadIdx.x;

    for (int i = tid; i < BB * CC; i += 256)
        hw_s[i >> 9][i & 511] = g_hw[i >> 9][k][i & 511];
    __syncthreads();

    const int e = e0 + (tid & 31);
    const int ds = (tid >> 5) * 64;
    float acc[BB];
#pragma unroll
    for (int b = 0; b < BB; b++) acc[b] = 0.f;

    const float* w2p = w2 + ((size_t)k * CC + ds) * CC + e;
#pragma unroll 4
    for (int d = 0; d < 64; d++) {
        float w = w2p[(size_t)d * CC];
#pragma unroll
        for (int b = 0; b < BB; b++) acc[b] += hw_s[b][ds + d] * w;
    }
#pragma unroll
    for (int b = 0; b < BB; b++) part[tid >> 5][tid & 31][b] = acc[b];
    __syncthreads();

    {
        const int b = tid >> 5, el = tid & 31;
        float s = 0.f;
#pragma unroll
        for (int sl = 0; sl < 8; sl++) s += part[sl][el][b];
        float mass = g_mass[b][k];
        float inv = 1.f / fmaxf(mass, EPSF);
        float val = (s + b2[k * CC + e0 + el] * mass) * inv;
        int o = (b * KK + k) * CC + e0 + el;
        if (o < out_size) out[o] = val;
    }

    if (blockIdx.x == 0 && blockIdx.y == 0 && tid == 0) {
        float usage[KK], mean = 0.f;
#pragma unroll
        for (int kk = 0; kk < KK; kk++) {
            int s = 0;
            for (int bb = 0; bb < BB; bb++) s += g_cnt[bb][kk];
            usage[kk] = (float)s / (float)(BB * NN);
            mean += usage[kk];
        }
        mean /= (float)KK;
        float var = 0.f;
#pragma unroll
        for (int kk = 0; kk < KK; kk++) { float d = usage[kk] - mean; var += d * d; }
        var /= (float)KK;
        float denom = mean + EPSF;
        out[out_size - 1] = var / (denom * denom);
    }
}

// ---------------- launch ----------------
extern "C" void kernel_launch(void* const* d_in, const int* in_sizes, int n_in,
                              void* d_out, int out_size) {
    const float* tokens   = (const float*)d_in[0];
    const float* geno_vec = (const float*)d_in[1];
    const float* gate_w   = (const float*)d_in[2];
    const float* gate_b   = (const float*)d_in[3];
    const float* geno_w   = (const float*)d_in[4];
    const float* geno_b   = (const float*)d_in[5];
    const float* w1       = (const float*)d_in[6];
    const float* b1       = (const float*)d_in[7];
    const float* w2       = (const float*)d_in[8];
    const float* b2       = (const float*)d_in[9];
    float* out = (float*)d_out;

    const int smem_bytes = (2 * STAGE_FLOATS) * 4 + BM * 8;
    cudaFuncSetAttribute(ffn1_mma_kernel, cudaFuncAttributeMaxDynamicSharedMemorySize, smem_bytes);

    prep_kernel<<<33, 256>>>(geno_vec, geno_w, geno_b);
    gate_kernel<<<(BB * NN + 7) / 8, 256>>>(tokens, gate_w, gate_b);
    {
        dim3 g(CC / BN, NN / BM, BB * KK);  // 2 x 16 x 64
        ffn1_mma_kernel<<<g, 256, smem_bytes>>>(tokens, w1, b1);
    }
    {
        dim3 g(KK, CC / 32);
        centers_kernel<<<g, 256>>>(w2, b2, out, out_size);
    }
}